// round 1
// baseline (speedup 1.0000x reference)
#include <cuda_runtime.h>

// DifferentiableCensus: out[p] = (1/9) * sum_{3x3 window, edge-clamped} sigmoid(neighbor - center)
// x: (16,3,512,512) f32 -> treat as 48 images of 512x512.
//
// Strategy (round 1):
//  - 1 thread = 1 column x 8 consecutive rows (register-rolling 3-wide x 3-row window).
//  - Center term = 0.5 (free).
//  - Vertical pairs shared across consecutive rows via sigmoid antisymmetry:
//      next row's "up" term = 1 - this row's "down" term.
//  - sigmoid via fast intrinsics: EX2 + RCP (2 MUFU each). ~7.1 sigmoids/px.

static constexpr int IMG_H = 512;
static constexpr int IMG_W = 512;
static constexpr int ROWS_PER_THREAD = 8;
static constexpr int BLOCK_X = 128;

__device__ __forceinline__ float fast_sigmoid(float d) {
    // 1 / (1 + e^-d): __expf -> FMUL+MUFU.EX2, __fdividef -> MUFU.RCP(+FMUL)
    return __fdividef(1.0f, 1.0f + __expf(-d));
}

__global__ __launch_bounds__(BLOCK_X)
void census_kernel(const float* __restrict__ x, float* __restrict__ out) {
    const int c   = blockIdx.x * BLOCK_X + threadIdx.x;   // column, 0..511
    const int r0  = blockIdx.y * ROWS_PER_THREAD;         // first row of strip
    const int img = blockIdx.z;                           // 0..47

    const float* __restrict__ xi = x   + (size_t)img * IMG_H * IMG_W;
    float* __restrict__       oi = out + (size_t)img * IMG_H * IMG_W;

    const int cm = max(c - 1, 0);
    const int cp = min(c + 1, IMG_W - 1);

    // Rolling window registers: row a = r-1 (clamped), row b = r (current center row).
    const int rm = max(r0 - 1, 0);
    float am = __ldg(xi + (size_t)rm * IMG_W + cm);
    float ac = __ldg(xi + (size_t)rm * IMG_W + c);
    float ap = __ldg(xi + (size_t)rm * IMG_W + cp);
    float bm = __ldg(xi + (size_t)r0 * IMG_W + cm);
    float bc = __ldg(xi + (size_t)r0 * IMG_W + c);
    float bp = __ldg(xi + (size_t)r0 * IMG_W + cp);

    // "up" vertical term for the first row of the strip.
    float up = fast_sigmoid(ac - bc);   // r0==0 -> ac==bc -> 0.5 (matches edge pad)

    #pragma unroll
    for (int k = 0; k < ROWS_PER_THREAD; k++) {
        const int r  = r0 + k;
        const int rn = min(r + 1, IMG_H - 1);

        const float nm = __ldg(xi + (size_t)rn * IMG_W + cm);
        const float nc = __ldg(xi + (size_t)rn * IMG_W + c);
        const float np = __ldg(xi + (size_t)rn * IMG_W + cp);

        const float down = fast_sigmoid(nc - bc);

        float acc = 0.5f + up + down;               // center + vertical pair
        acc += fast_sigmoid(bm - bc);               // left
        acc += fast_sigmoid(bp - bc);               // right
        acc += fast_sigmoid(am - bc);               // up-left
        acc += fast_sigmoid(ap - bc);               // up-right
        acc += fast_sigmoid(nm - bc);               // down-left
        acc += fast_sigmoid(np - bc);               // down-right

        oi[(size_t)r * IMG_W + c] = acc * (1.0f / 9.0f);

        // Next row's up term: sigmoid(x[r] - x[r+1]) = 1 - sigmoid(x[r+1] - x[r])
        up = 1.0f - down;
        am = bm; ac = bc; ap = bp;
        bm = nm; bc = nc; bp = np;
    }
}

extern "C" void kernel_launch(void* const* d_in, const int* in_sizes, int n_in,
                              void* d_out, int out_size) {
    (void)in_sizes; (void)n_in; (void)out_size;
    const float* x = (const float*)d_in[0];
    float* out = (float*)d_out;

    dim3 block(BLOCK_X, 1, 1);
    dim3 grid(IMG_W / BLOCK_X, IMG_H / ROWS_PER_THREAD, 16 * 3);
    census_kernel<<<grid, block>>>(x, out);
}

// round 2
// speedup vs baseline: 1.7043x; 1.7043x over previous
#include <cuda_runtime.h>

// DifferentiableCensus: out = (1/9) * sum_{3x3, edge-clamped} sigmoid(neighbor - center)
// x: (16,3,512,512) f32 -> 48 independent 512x512 images.
//
// Round 2 strategy:
//  - sigmoid(d) = 0.5 + 0.5*tanh(d/2): tanh.approx.f32 = ONE MUFU op per sigmoid.
//    Accumulate raw tanh values T; out = 0.5 + T/18 (constants folded).
//  - 1 thread = 4 cols x 8 rows register tile. Each unordered pixel-pair edge
//    is computed ONCE; the reverse term is the negation (1 - sig(d) = sig(-d)
//    -> -tanh). Vertical, horizontal and BOTH diagonals shared in-thread via
//    carried registers: 19 tanh per 4-px row (4.75/px) + 12 priming per strip.
//  - Inputs pre-scaled by 0.5 at load so tanh argument is a single FADD.
//  - float4 loads/stores; edge clamp handled by clamped halo loads (the
//    algebra then reproduces jnp.pad(mode='edge') automatically).

static constexpr int H = 512;
static constexpr int W = 512;
static constexpr int ROWS_PER_THREAD = 8;
static constexpr int BLOCK_X = 128;            // 128 threads * 4 cols = 512 cols

__device__ __forceinline__ float tanh_approx(float v) {
    float r;
    asm("tanh.approx.f32 %0, %1;" : "=f"(r) : "f"(v));
    return r;
}

__device__ __forceinline__ void load_row(const float* __restrict__ row,
                                         int c0, int cl, int cr, float v[6]) {
    // v[0] = col c0-1 (clamped), v[1..4] = cols c0..c0+3, v[5] = col c0+4 (clamped)
    const float4 m = __ldg(reinterpret_cast<const float4*>(row + c0));
    v[0] = 0.5f * __ldg(row + cl);
    v[1] = 0.5f * m.x;
    v[2] = 0.5f * m.y;
    v[3] = 0.5f * m.z;
    v[4] = 0.5f * m.w;
    v[5] = 0.5f * __ldg(row + cr);
}

__global__ __launch_bounds__(BLOCK_X)
void census_kernel(const float* __restrict__ x, float* __restrict__ out) {
    const int c0  = threadIdx.x * 4;                  // first owned column
    const int r0  = blockIdx.y * ROWS_PER_THREAD;     // first owned row
    const int img = blockIdx.z;

    const float* __restrict__ xi = x   + (size_t)img * H * W;
    float* __restrict__       oi = out + (size_t)img * H * W;

    const int cl = max(c0 - 1, 0);
    const int cr = min(c0 + 4, W - 1);

    float p[6], b[6];                                  // rows r-1, r (prescaled by 0.5)
    load_row(xi + (size_t)max(r0 - 1, 0) * W, c0, cl, cr, p);
    load_row(xi + (size_t)r0 * W,             c0, cl, cr, b);

    // Priming carries: edge tanh values of row r0-1 (S / SE / SW of row r0-1).
    // At r0==0, p==b row -> values reduce to the correct clamped-edge terms.
    float pS[4], pDR[4], pDL[4];
    #pragma unroll
    for (int i = 0; i < 4; i++) {
        pS[i]  = tanh_approx(b[i + 1] - p[i + 1]);     // S(r0-1, c0+i)
        pDR[i] = tanh_approx(b[i + 2] - p[i + 1]);     // SE(r0-1, c0+i)
        pDL[i] = tanh_approx(b[i]     - p[i + 1]);     // SW(r0-1, c0+i)
    }

    #pragma unroll
    for (int k = 0; k < ROWS_PER_THREAD; k++) {
        const int r = r0 + k;
        float n[6];                                    // row r+1 (clamped)
        load_row(xi + (size_t)min(r + 1, H - 1) * W, c0, cl, cr, n);

        float tS[4], tDR[4], tDL[4], tE[4];
        #pragma unroll
        for (int i = 0; i < 4; i++) {
            tS[i]  = tanh_approx(n[i + 1] - b[i + 1]); // S  of col c0+i
            tDR[i] = tanh_approx(n[i + 2] - b[i + 1]); // SE of col c0+i
            tDL[i] = tanh_approx(n[i]     - b[i + 1]); // SW of col c0+i
            tE[i]  = tanh_approx(b[i + 2] - b[i + 1]); // E  of col c0+i
        }
        const float tW0  = tanh_approx(b[0] - b[1]);   // W  of col c0   (left halo)
        const float tUL0 = tanh_approx(p[0] - b[1]);   // NW of col c0   (left halo)
        const float tUR3 = tanh_approx(p[5] - b[4]);   // NE of col c0+3 (right halo)

        // T = sum of signed tanh over the 8 neighbor terms.
        //  forward edges: +t ; reverse of an already-computed edge: -t
        const float T0 = (tS[0] + tDR[0]) + (tDL[0] - pS[0])
                       + (tE[0] + tW0)    + (tUL0   - pDL[1]);
        const float T1 = (tS[1] + tDR[1]) + (tDL[1] - pS[1])
                       + (tE[1] - tE[0])  - (pDR[0] + pDL[2]);
        const float T2 = (tS[2] + tDR[2]) + (tDL[2] - pS[2])
                       + (tE[2] - tE[1])  - (pDR[1] + pDL[3]);
        const float T3 = (tS[3] + tDR[3]) + (tDL[3] - pS[3])
                       + (tE[3] - tE[2])  + (tUR3   - pDR[2]);

        float4 o;
        o.x = fmaf(T0, 1.0f / 18.0f, 0.5f);
        o.y = fmaf(T1, 1.0f / 18.0f, 0.5f);
        o.z = fmaf(T2, 1.0f / 18.0f, 0.5f);
        o.w = fmaf(T3, 1.0f / 18.0f, 0.5f);
        *reinterpret_cast<float4*>(oi + (size_t)r * W + c0) = o;

        // Roll rows and carries.
        #pragma unroll
        for (int i = 0; i < 6; i++) { p[i] = b[i]; b[i] = n[i]; }
        #pragma unroll
        for (int i = 0; i < 4; i++) { pS[i] = tS[i]; pDR[i] = tDR[i]; pDL[i] = tDL[i]; }
    }
}

extern "C" void kernel_launch(void* const* d_in, const int* in_sizes, int n_in,
                              void* d_out, int out_size) {
    (void)in_sizes; (void)n_in; (void)out_size;
    const float* x = (const float*)d_in[0];
    float* out = (float*)d_out;

    dim3 block(BLOCK_X, 1, 1);
    dim3 grid(1, H / ROWS_PER_THREAD, 16 * 3);
    census_kernel<<<grid, block>>>(x, out);
}